// round 10
// baseline (speedup 1.0000x reference)
#include <cuda_runtime.h>
#include <cuda_bf16.h>
#include <math.h>

// Problem constants (fixed by reference setup_inputs)
#define N_TOK   4096        // B*S = 2*2048
#define DIM     1024
#define NEXP    8
#define CAP     1280        // floor(2*1.25*4096/8), even
#define ECAP    (NEXP*CAP)  // 10240
#define NASSIGN (2*N_TOK)   // 8192

// Output layout (floats), concatenated in reference return order:
//  W  : [N, E, CAP],  M : [N, E, CAP],  Bt : [E, CAP, DIM],  L : [N, E]
#define OFF_W  ((size_t)0)
#define OFF_M  ((size_t)N_TOK * NEXP * CAP)
#define OFF_B  (OFF_M + (size_t)N_TOK * NEXP * CAP)
#define OFF_L  (OFF_B + (size_t)NEXP * CAP * DIM)

// Zero-fill geometry: W+M = 83,886,080 floats = 20,971,520 float4
#define ZERO_BLOCKS 2560
#define ZERO_THREADS 512
#define ZERO_ITERS  16      // 2560 * 512 * 16 = 20,971,520 float4

// Scratch (__device__ globals; no allocation allowed)
__device__ int   g_slot_token[ECAP];          // slot -> token, -1 = empty
__device__ int   g_sel [2][N_TOK];            // selected expert per (k, token)
__device__ float g_prob[2][N_TOK];            // gating prob per (k, token)
__device__ int   g_patch_off[NASSIGN];        // flat W/M offset, -1 = dropped

// ---------------------------------------------------------------------------
// kZero: contiguous 128KB per block, coalesced 16B streaming stores.
// ---------------------------------------------------------------------------
__global__ void kZero(float4* __restrict__ P)
{
    const size_t base = (size_t)blockIdx.x * (ZERO_THREADS * ZERO_ITERS) + threadIdx.x;
    const float4 z = make_float4(0.f, 0.f, 0.f, 0.f);
#pragma unroll
    for (int i = 0; i < ZERO_ITERS; ++i)
        __stcs(P + base + (size_t)i * ZERO_THREADS, z);
}

// ---------------------------------------------------------------------------
// kA: one token per BLOCK (4096 blocks x 256 threads). Whole-D parallelism:
// each thread does 1 x-float4 + 8 (L1-resident) w-float4, cross-warp smem
// reduction, then lane work for top-2 gating. Writes L, g_sel, g_prob.
// ---------------------------------------------------------------------------
__global__ void kA_gate(const float4* __restrict__ X4,
                        const float4* __restrict__ G4,
                        float* __restrict__ L)
{
    __shared__ float red[8][NEXP];
    __shared__ float logits[NEXP];

    const int tid  = threadIdx.x;
    const int warp = tid >> 5;
    const int lane = tid & 31;
    const int n = blockIdx.x;

    const float4 xv = X4[(size_t)n * 256 + tid];

    float acc[NEXP];
#pragma unroll
    for (int e = 0; e < NEXP; ++e) {
        const float4 wv = G4[e * 256 + tid];
        acc[e] = xv.x * wv.x + xv.y * wv.y + xv.z * wv.z + xv.w * wv.w;
    }
#pragma unroll
    for (int e = 0; e < NEXP; ++e) {
#pragma unroll
        for (int s = 16; s > 0; s >>= 1)
            acc[e] += __shfl_xor_sync(0xffffffffu, acc[e], s);
    }
    if (lane == 0) {
#pragma unroll
        for (int e = 0; e < NEXP; ++e) red[warp][e] = acc[e];
    }
    __syncthreads();

    if (warp == 0) {
        if (lane < NEXP) {
            float s = 0.f;
#pragma unroll
            for (int w = 0; w < 8; ++w) s += red[w][lane];
            logits[lane] = s;
            L[(size_t)n * NEXP + lane] = s;
        }
        __syncwarp();
        if (lane == 0) {
            // top-1 (ties -> lowest index, matching lax.top_k)
            int i1 = 0; float v1 = logits[0];
#pragma unroll
            for (int e = 1; e < NEXP; ++e) if (logits[e] > v1) { v1 = logits[e]; i1 = e; }
            int i2 = -1; float v2 = -INFINITY;
#pragma unroll
            for (int e = 0; e < NEXP; ++e)
                if (e != i1 && logits[e] > v2) { v2 = logits[e]; i2 = e; }

            const float mx = fmaxf(v1, v2);
            const float e1 = expf(v1 - mx), e2 = expf(v2 - mx);
            const float inv = 1.f / (e1 + e2);
            g_prob[0][n] = e1 * inv;
            g_prob[1][n] = e2 * inv;
            g_sel[0][n] = i1;
            g_sel[1][n] = i2;
        }
    }
}

// ---------------------------------------------------------------------------
// kRoute (1 block, 256 thr): slot init + ordered k-major ranking via
// warp-per-expert ballot scan over g_sel (4x front-batched loads).
// Produces g_slot_token and g_patch_off.
// ---------------------------------------------------------------------------
__global__ void kRoute()
{
    const int tid  = threadIdx.x;
    const int e    = tid >> 5;           // expert (8 warps)
    const int lane = tid & 31;
    const unsigned lt_mask = (1u << lane) - 1u;

    // init slot map
    for (int i = tid; i < ECAP; i += 256) g_slot_token[i] = -1;
    __syncthreads();

    int carry = 0;                       // running count for expert e (k-major)
#pragma unroll 1
    for (int k = 0; k < 2; ++k) {
        const int* sel_k = g_sel[k];
#pragma unroll 1
        for (int c0 = 0; c0 < N_TOK; c0 += 128) {
            // front-batch 4 chunks (hide L2 latency)
            const int s0 = sel_k[c0 +       lane];
            const int s1 = sel_k[c0 + 32  + lane];
            const int s2 = sel_k[c0 + 64  + lane];
            const int s3 = sel_k[c0 + 96  + lane];

            const int ss[4] = {s0, s1, s2, s3};
#pragma unroll
            for (int j = 0; j < 4; ++j) {
                const unsigned b = __ballot_sync(0xffffffffu, ss[j] == e);
                if (ss[j] == e) {
                    const int n = c0 + 32 * j + lane;
                    const int rank = carry + __popc(b & lt_mask);
                    int off = -1;
                    if (rank < CAP) {
                        off = n * ECAP + e * CAP + rank;   // < 2^26, fits int
                        g_slot_token[e * CAP + rank] = n;
                    }
                    g_patch_off[k * N_TOK + n] = off;
                }
                carry += __popc(b);
            }
        }
    }
}

// ---------------------------------------------------------------------------
// k3: fill expert_batches [E*CAP, DIM]: token row if occupied, zeros otherwise.
// Runs on s0 concurrent with kZero (independent of the W/M zeroing).
// ---------------------------------------------------------------------------
__global__ void k3_batches(const float4* __restrict__ X4,
                           float4* __restrict__ B4)
{
    const int slot = blockIdx.x;             // e*CAP + c
    const int t = g_slot_token[slot];        // broadcast load
    const int i = threadIdx.x;               // 0..255 (DIM/4)
    float4 out;
    if (t >= 0) out = X4[(size_t)t * 256 + i];
    else        out = make_float4(0.f, 0.f, 0.f, 0.f);
    __stcs(B4 + (size_t)slot * 256 + i, out);
}

// ---------------------------------------------------------------------------
// kC: tiny coalesced patch scatter into zeroed W/M. 32 blocks x 256 thr.
// ---------------------------------------------------------------------------
__global__ void kC_patch(float* __restrict__ W, float* __restrict__ M)
{
    const int i = blockIdx.x * 256 + threadIdx.x;   // 0..8191, k-major
    const int off = __ldg(&g_patch_off[i]);
    const float v = g_prob[i >> 12][i & (N_TOK - 1)];
    if (off >= 0) {
        W[off] = v;
        M[off] = 1.0f;
    }
}

// ---------------------------------------------------------------------------
extern "C" void kernel_launch(void* const* d_in, const int* in_sizes, int n_in,
                              void* d_out, int out_size)
{
    const float* x      = (const float*)d_in[0];   // [2,2048,1024]
    const float* w_gate = (const float*)d_in[1];   // [8,1024]
    float* out = (float*)d_out;

    float* W  = out + OFF_W;
    float* M  = out + OFF_M;
    float* Bt = out + OFF_B;
    float* L  = out + OFF_L;

    cudaStream_t s2;
    cudaEvent_t ev_fork, ev_route, ev_done;
    cudaStreamCreateWithFlags(&s2, cudaStreamNonBlocking);
    cudaEventCreateWithFlags(&ev_fork,  cudaEventDisableTiming);
    cudaEventCreateWithFlags(&ev_route, cudaEventDisableTiming);
    cudaEventCreateWithFlags(&ev_done,  cudaEventDisableTiming);

    // Serial prefix: kA runs ALONE (contending with kZero proven slower).
    kA_gate<<<N_TOK, 256>>>((const float4*)x, (const float4*)w_gate, L);

    // Fork AFTER kA: kZero occupies the machine while the small chain runs.
    cudaEventRecord(ev_fork, 0);
    cudaStreamWaitEvent(s2, ev_fork, 0);
    kZero<<<ZERO_BLOCKS, ZERO_THREADS, 0, s2>>>((float4*)out);

    // s0: routing + Bt fill (concurrent with kZero)
    kRoute<<<1, 256>>>();
    cudaEventRecord(ev_route, 0);
    k3_batches<<<ECAP, 256>>>((const float4*)x, (float4*)Bt);

    // s2: patch directly after kZero (needs routing results -> wait ev_route)
    cudaStreamWaitEvent(s2, ev_route, 0);
    kC_patch<<<NASSIGN / 256, 256, 0, s2>>>(W, M);

    // Join s2 back into the capture origin stream (required for capture).
    cudaEventRecord(ev_done, s2);
    cudaStreamWaitEvent(0, ev_done, 0);
}

// round 13
// speedup vs baseline: 1.2188x; 1.2188x over previous
#include <cuda_runtime.h>
#include <cuda_bf16.h>
#include <math.h>

// Problem constants (fixed by reference setup_inputs)
#define N_TOK   4096        // B*S = 2*2048
#define DIM     1024
#define NEXP    8
#define CAP     1280        // floor(2*1.25*4096/8), even
#define ECAP    (NEXP*CAP)  // 10240
#define TPB     16          // tokens per block in phase A
#define NCHUNK  (N_TOK/TPB) // 256 blocks in phase A
#define NASSIGN (2*N_TOK)   // 8192

// Output layout (floats), concatenated in reference return order:
//  W  : [N, E, CAP],  M : [N, E, CAP],  Bt : [E, CAP, DIM],  L : [N, E]
#define OFF_W  ((size_t)0)
#define OFF_M  ((size_t)N_TOK * NEXP * CAP)
#define OFF_B  (OFF_M + (size_t)N_TOK * NEXP * CAP)
#define OFF_L  (OFF_B + (size_t)NEXP * CAP * DIM)

// Zero-fill geometry: W+M = 83,886,080 floats = 20,971,520 float4
#define ZERO_BLOCKS 2560
#define ZERO_THREADS 512
#define ZERO_ITERS  16      // 2560 * 512 * 16 = 20,971,520 float4

// Scratch (__device__ globals; no allocation allowed)
__device__ int   g_slot_token[ECAP];          // slot -> token, -1 = empty
__device__ int   g_cnt [NCHUNK][2][NEXP];     // per-chunk per-k per-expert counts
__device__ int   g_meta[2][N_TOK];            // e | (in_chunk_rank << 8)
__device__ float g_prob[2][N_TOK];            // gating prob of the assignment
__device__ int   g_patch_off[NASSIGN];        // flat W/M offset, -1 = dropped
__device__ float g_patch_val[NASSIGN];        // prob to write

// ---------------------------------------------------------------------------
// kZero: contiguous 128KB per block, coalesced 16B streaming stores.
// ---------------------------------------------------------------------------
__global__ void kZero(float4* __restrict__ P)
{
    const size_t base = (size_t)blockIdx.x * (ZERO_THREADS * ZERO_ITERS) + threadIdx.x;
    const float4 z = make_float4(0.f, 0.f, 0.f, 0.f);
#pragma unroll
    for (int i = 0; i < ZERO_ITERS; ++i)
        __stcs(P + base + (size_t)i * ZERO_THREADS, z);
}

// ---------------------------------------------------------------------------
// Phase A: fused logits + top-2 gating + per-chunk counts / in-chunk ranks.
// grid = 256, block = 256 (8 warps); each warp handles TWO tokens.
// ALL 16 x-float4 loads are front-batched (MLP=16) before the FMA loop;
// w_gate float4s are L1-resident and reused for both tokens.
// ---------------------------------------------------------------------------
__global__ void kA_gate(const float4* __restrict__ X4,
                        const float4* __restrict__ G4,
                        float* __restrict__ L)
{
    __shared__ int s_sel[2][TPB];

    const int warp = threadIdx.x >> 5;
    const int lane = threadIdx.x & 31;
    const int n0 = blockIdx.x * TPB + warp * 2;    // first of two tokens

    // front-batch: 16 outstanding LDG.128 per thread
    float4 xv0[8], xv1[8];
#pragma unroll
    for (int i = 0; i < 8; ++i)
        xv0[i] = X4[(size_t)n0 * 256 + 32 * i + lane];
#pragma unroll
    for (int i = 0; i < 8; ++i)
        xv1[i] = X4[(size_t)(n0 + 1) * 256 + 32 * i + lane];

    float acc0[NEXP], acc1[NEXP];
#pragma unroll
    for (int e = 0; e < NEXP; ++e) {
        float a0 = 0.f, a1 = 0.f;
#pragma unroll
        for (int i = 0; i < 8; ++i) {
            const float4 wv = G4[e * 256 + 32 * i + lane];
            a0 += xv0[i].x * wv.x + xv0[i].y * wv.y + xv0[i].z * wv.z + xv0[i].w * wv.w;
            a1 += xv1[i].x * wv.x + xv1[i].y * wv.y + xv1[i].z * wv.z + xv1[i].w * wv.w;
        }
        acc0[e] = a0;
        acc1[e] = a1;
    }
#pragma unroll
    for (int e = 0; e < NEXP; ++e) {
#pragma unroll
        for (int s = 16; s > 0; s >>= 1) {
            acc0[e] += __shfl_xor_sync(0xffffffffu, acc0[e], s);
            acc1[e] += __shfl_xor_sync(0xffffffffu, acc1[e], s);
        }
    }

    if (lane == 0) {
#pragma unroll
        for (int t = 0; t < 2; ++t) {
            const int n = n0 + t;
            const float* acc = t ? acc1 : acc0;
            ((float4*)L)[(size_t)n * 2 + 0] = make_float4(acc[0], acc[1], acc[2], acc[3]);
            ((float4*)L)[(size_t)n * 2 + 1] = make_float4(acc[4], acc[5], acc[6], acc[7]);

            int i1 = 0; float v1 = acc[0];
#pragma unroll
            for (int e = 1; e < NEXP; ++e) if (acc[e] > v1) { v1 = acc[e]; i1 = e; }
            int i2 = -1; float v2 = -INFINITY;
#pragma unroll
            for (int e = 0; e < NEXP; ++e)
                if (e != i1 && acc[e] > v2) { v2 = acc[e]; i2 = e; }

            const float mx = fmaxf(v1, v2);
            const float e1 = expf(v1 - mx), e2 = expf(v2 - mx);
            const float inv = 1.f / (e1 + e2);
            g_prob[0][n] = e1 * inv;
            g_prob[1][n] = e2 * inv;
            s_sel[0][warp * 2 + t] = i1;
            s_sel[1][warp * 2 + t] = i2;
        }
    }
    __syncthreads();

    if (threadIdx.x < 2 * TPB) {          // in-chunk ranks (32 assignments)
        const int k = threadIdx.x >> 4;
        const int t = threadIdx.x & (TPB - 1);
        const int e = s_sel[k][t];
        int r = 0;
#pragma unroll
        for (int w = 0; w < TPB; ++w) r += (w < t) && (s_sel[k][w] == e);
        g_meta[k][blockIdx.x * TPB + t] = e | (r << 8);
    }
    if (threadIdx.x >= 64 && threadIdx.x < 80) {   // per-chunk counts (16 pairs)
        const int idx = threadIdx.x - 64;
        const int k = idx >> 3;
        const int e = idx & 7;
        int c = 0;
#pragma unroll
        for (int w = 0; w < TPB; ++w) c += (s_sel[k][w] == e);
        g_cnt[blockIdx.x][k][e] = c;
    }
}

// ---------------------------------------------------------------------------
// kRoute (1 block, 256 thr): slot init + k-major prefix scan + slot scatter
// + patch-list build.
// ---------------------------------------------------------------------------
__global__ void kRoute()
{
    __shared__ int s_base[NCHUNK][2][NEXP];   // 16 KB: per-chunk exclusive bases

    const int tid  = threadIdx.x;
    const int e    = tid >> 5;           // expert (8 warps)
    const int lane = tid & 31;

    // init slot map
    for (int i = tid; i < ECAP; i += 256) g_slot_token[i] = -1;

    // exclusive k-major prefix over chunk counts (warp e owns expert e)
    int carry = 0;
    for (int k = 0; k < 2; ++k) {
        for (int c0 = 0; c0 < NCHUNK; c0 += 32) {
            const int v = g_cnt[c0 + lane][k][e];
            int inc = v;
#pragma unroll
            for (int s = 1; s < 32; s <<= 1) {
                const int t = __shfl_up_sync(0xffffffffu, inc, s);
                if (lane >= s) inc += t;
            }
            s_base[c0 + lane][k][e] = carry + (inc - v);
            carry += __shfl_sync(0xffffffffu, inc, 31);
        }
    }
    __syncthreads();

    // scatter slot -> token and build patch list (8192 assignments)
#pragma unroll 4
    for (int idx = tid; idx < NASSIGN; idx += 256) {
        const int k = idx >> 12;
        const int n = idx & (N_TOK - 1);
        const int meta = g_meta[k][n];
        const int ee = meta & 255;
        const int r  = meta >> 8;
        const int rank = s_base[n / TPB][k][ee] + r;
        int off = -1;
        if (rank < CAP) {
            off = n * ECAP + ee * CAP + rank;          // < 2^26, fits int
            g_slot_token[ee * CAP + rank] = n;
        }
        g_patch_off[idx] = off;
        g_patch_val[idx] = g_prob[k][n];
    }
}

// ---------------------------------------------------------------------------
// k3: fill expert_batches [E*CAP, DIM]: token row if occupied, zeros otherwise.
// Runs on s0 concurrent with kZero (independent of the W/M zeroing).
// ---------------------------------------------------------------------------
__global__ void k3_batches(const float4* __restrict__ X4,
                           float4* __restrict__ B4)
{
    const int slot = blockIdx.x;             // e*CAP + c
    const int t = g_slot_token[slot];        // broadcast load
    const int i = threadIdx.x;               // 0..255 (DIM/4)
    float4 out;
    if (t >= 0) out = X4[(size_t)t * 256 + i];
    else        out = make_float4(0.f, 0.f, 0.f, 0.f);
    __stcs(B4 + (size_t)slot * 256 + i, out);
}

// ---------------------------------------------------------------------------
// kC: tiny coalesced patch scatter into zeroed W/M. 32 blocks x 256 thr.
// ---------------------------------------------------------------------------
__global__ void kC_patch(float* __restrict__ W, float* __restrict__ M)
{
    const int i = blockIdx.x * 256 + threadIdx.x;   // 0..8191
    const int off = __ldg(&g_patch_off[i]);
    const float v = __ldg(&g_patch_val[i]);
    if (off >= 0) {
        W[off] = v;
        M[off] = 1.0f;
    }
}

// ---------------------------------------------------------------------------
extern "C" void kernel_launch(void* const* d_in, const int* in_sizes, int n_in,
                              void* d_out, int out_size)
{
    const float* x      = (const float*)d_in[0];   // [2,2048,1024]
    const float* w_gate = (const float*)d_in[1];   // [8,1024]
    float* out = (float*)d_out;

    float* W  = out + OFF_W;
    float* M  = out + OFF_M;
    float* Bt = out + OFF_B;
    float* L  = out + OFF_L;

    cudaStream_t s2;
    cudaEvent_t ev_fork, ev_route, ev_done;
    cudaStreamCreateWithFlags(&s2, cudaStreamNonBlocking);
    cudaEventCreateWithFlags(&ev_fork,  cudaEventDisableTiming);
    cudaEventCreateWithFlags(&ev_route, cudaEventDisableTiming);
    cudaEventCreateWithFlags(&ev_done,  cudaEventDisableTiming);

    // Serial prefix: kA runs ALONE (pure-read phase; mixing with the store
    // flood is proven slower).
    kA_gate<<<NCHUNK, 256>>>((const float4*)x, (const float4*)w_gate, L);

    // Fork AFTER kA: kZero occupies the machine while the small chain runs.
    cudaEventRecord(ev_fork, 0);
    cudaStreamWaitEvent(s2, ev_fork, 0);
    kZero<<<ZERO_BLOCKS, ZERO_THREADS, 0, s2>>>((float4*)out);

    // s0: routing + Bt fill (concurrent with kZero)
    kRoute<<<1, 256>>>();
    cudaEventRecord(ev_route, 0);
    k3_batches<<<ECAP, 256>>>((const float4*)x, (float4*)Bt);

    // s2: patch directly after kZero (needs routing results -> wait ev_route)
    cudaStreamWaitEvent(s2, ev_route, 0);
    kC_patch<<<NASSIGN / 256, 256, 0, s2>>>(W, M);

    // Join s2 back into the capture origin stream (required for capture).
    cudaEventRecord(ev_done, s2);
    cudaStreamWaitEvent(0, ev_done, 0);
}